// round 17
// baseline (speedup 1.0000x reference)
#include <cuda_runtime.h>
#include <math.h>

#define BB   32
#define SS   512
#define HH   512
#define EE   512
#define NTHR 512

// ---------- global scratch ----------
__device__ unsigned long long g_ht2[2][256][BB];   // [buf][jpair][b]
__device__ unsigned g_gen8[8];                      // counter g: CTAs [16g,16g+16)

union F2U { unsigned long long u; float2 f; };

__device__ __forceinline__ unsigned long long ffma2u(unsigned long long a,
                                                     unsigned long long b,
                                                     unsigned long long c) {
    unsigned long long d;
    asm("fma.rn.f32x2 %0, %1, %2, %3;" : "=l"(d) : "l"(a), "l"(b), "l"(c));
    return d;
}

__device__ __forceinline__ unsigned ld_acq(const unsigned* p) {
    unsigned v;
    asm volatile("ld.global.acquire.gpu.u32 %0, [%1];" : "=r"(v) : "l"(p) : "memory");
    return v;
}
__device__ __forceinline__ void red_release_add(unsigned* p, unsigned v) {
    asm volatile("red.release.gpu.global.add.u32 [%0], %1;" :: "l"(p), "r"(v) : "memory");
}
__device__ __forceinline__ void bar_sync(int id, int cnt) {
    asm volatile("bar.sync %0, %1;" :: "r"(id), "r"(cnt) : "memory");
}

__device__ __forceinline__ float fast_sigmoid(float x) {
    return __fdividef(1.0f, 1.0f + __expf(-x));
}
__device__ __forceinline__ float fast_tanh(float x) {
    return __fdividef(2.0f, 1.0f + __expf(-2.0f * x)) - 1.0f;
}

__global__ void reset_gen_kernel() {
    if (threadIdx.x < 8) g_gen8[threadIdx.x] = 0u;
}

// ======================================================================
// Warp-specialized persistent LSTM (hardened sync): 128 CTAs x 512 thr.
// Warps 0-7  = REC: serial chain (poll, gather h, rec-FMA K=64/warp,
//              reduce+nonlin+publish on warps 0-3).
// Warps 8-15 = EMB: emb-gate GEMM for step t+1 into ring[(t+1)&1],
//              stage tokens t+2. Joined ONLY by end-of-step __syncthreads.
// Sync: bar 1 = REC subset (256), bar 2 = EMB subset (256),
//       bar 3 = reducers (128), bar 0 = __syncthreads (512). No bar.arrive.
// ======================================================================
#define OFF_W     0         // 16*512 u64 = 65536
#define OFF_PART  65536     // 16*8*32 f32 = 16384   [r][w8][b32]
#define OFF_EPART 81920     // 16*8*32 f32 = 16384   [r][we8][b32]
#define OFF_RING  98304     // 2*16*32 f32 = 4096    [slot][r][b]
#define OFF_X     102400    // 8192 u64 = 65536      (single buffer, swizzled)
#define OFF_CNS   167936    // 16*32 f32 = 2048
#define OFF_C0    169984    // 4*32 f32 = 512
#define SMEM_TOT  170496

__global__ __launch_bounds__(NTHR, 1)
void lstm_ws_kernel(const int* __restrict__ seq,
                    const float* __restrict__ enc_h,
                    const float* __restrict__ enc_c,
                    const float* __restrict__ emb_table,
                    const float* __restrict__ W_ih,
                    const float* __restrict__ W_hh,
                    const float* __restrict__ b_ih,
                    const float* __restrict__ b_hh,
                    float* __restrict__ out)
{
    extern __shared__ char smem[];
    unsigned long long* w2_sh  = (unsigned long long*)(smem + OFF_W);
    float*              partf  = (float*)(smem + OFF_PART);
    float*              epart  = (float*)(smem + OFF_EPART);
    float*              ring   = (float*)(smem + OFF_RING);
    unsigned long long* x_sh   = (unsigned long long*)(smem + OFF_X);
    float*              cns_sh = (float*)(smem + OFF_CNS);
    float*              c0_sh  = (float*)(smem + OFF_C0);

    const int tid = threadIdx.x;
    const int bid = blockIdx.x;
    const int b   = tid & 31;
    const int j0  = bid * 4;

    // ---- prologue: weights + c0 ----
    for (int idx = tid; idx < 16 * 512; idx += NTHR) {
        int r  = idx >> 9;
        int kp = idx & 511;
        int grow = (r >> 2) * HH + j0 + (r & 3);
        w2_sh[idx] = ((const unsigned long long*)(W_ih + (size_t)grow * (EE + HH)))[kp];
    }
    if (tid < 128) c0_sh[(tid >> 5) * BB + b] = enc_c[b * HH + j0 + (tid >> 5)];
    __syncthreads();

    {   // cns = h0 @ W_hh^T + b_ih + b_hh (scratch: x region)
        float* scr = (float*)(smem + OFF_X);
        const int ks = tid >> 5;
        float h0c[32];
        #pragma unroll
        for (int i = 0; i < 32; i++) h0c[i] = enc_h[b * HH + ks * 32 + i];
        #pragma unroll
        for (int r = 0; r < 16; r++) {
            const float* wr = W_hh + (size_t)((r >> 2) * HH + j0 + (r & 3)) * HH + ks * 32;
            float acc = 0.f;
            #pragma unroll
            for (int i = 0; i < 32; i++) acc = fmaf(h0c[i], wr[i], acc);
            scr[r * 512 + ks * 32 + b] = acc;
        }
        __syncthreads();
        {
            float s = 0.f;
            #pragma unroll
            for (int k2 = 0; k2 < 16; k2++) s += scr[ks * 512 + k2 * 32 + b];
            int grow = (ks >> 2) * HH + j0 + (ks & 3);
            cns_sh[ks * BB + b] = s + b_ih[grow] + b_hh[grow];
        }
        __syncthreads();
    }

    // ---- prologue: stage tokens(0), compute ring[0], stage tokens(1) ----
    {
        // stage x <- tokens(0): thread covers 16 (kp,r32) cells, coalesced
        #pragma unroll
        for (int i = 0; i < 16; i++) {
            int n   = i * NTHR + tid;
            int r32 = n >> 8;
            int kp  = n & 255;
            int token = __ldg(&seq[r32 * SS + 0]);
            x_sh[kp * 32 + (r32 ^ (kp & 31))] = __ldg(
                (const unsigned long long*)(emb_table + (size_t)token * EE) + kp);
        }
        __syncthreads();

        // emb gates for t=0 (16-way split, all threads), scratch = PART+EPART
        float* scr2 = (float*)(smem + OFF_PART);   // 16*512 f32 contiguous
        const int ks = tid >> 5;
        unsigned long long x[16];
        #pragma unroll
        for (int i = 0; i < 16; i++) {
            int kp = ks * 16 + i;
            x[i] = x_sh[kp * 32 + (b ^ (kp & 31))];
        }
        unsigned long long acc[16];
        #pragma unroll
        for (int r = 0; r < 16; r++) acc[r] = 0ull;
        #pragma unroll
        for (int i2 = 0; i2 < 8; i2++) {
            unsigned long long xa = x[2 * i2], xb = x[2 * i2 + 1];
            #pragma unroll
            for (int r = 0; r < 16; r++) {
                ulonglong2 wv = *(const ulonglong2*)(w2_sh + r * 512 + ks * 16 + 2 * i2);
                acc[r] = ffma2u(xa, wv.x, ffma2u(xb, wv.y, acc[r]));
            }
        }
        #pragma unroll
        for (int r = 0; r < 16; r++) {
            F2U a; a.u = acc[r];
            scr2[r * 512 + ks * 32 + b] = a.f.x + a.f.y;
        }
        __syncthreads();
        {   // reduce into ring[0]
            int r = tid >> 5;
            float s = 0.f;
            #pragma unroll
            for (int k2 = 0; k2 < 16; k2++) s += scr2[r * 512 + k2 * 32 + b];
            ring[r * 32 + b] = s;
        }
        __syncthreads();

        // stage x <- tokens(1) (overwrites tokens(0); gates0 already banked)
        #pragma unroll
        for (int i = 0; i < 16; i++) {
            int n   = i * NTHR + tid;
            int r32 = n >> 8;
            int kp  = n & 255;
            int token = __ldg(&seq[r32 * SS + 1]);
            x_sh[kp * 32 + (r32 ^ (kp & 31))] = __ldg(
                (const unsigned long long*)(emb_table + (size_t)token * EE) + kp);
        }
        __syncthreads();
    }

    for (int t = 0; t < SS; t++) {
        if (tid < 256) {
            // ================= REC group =================
            const int w = tid >> 5;      // 0..7, h-pairs [32w, 32w+32)
            if (t > 0) {
                if ((tid & 31) == 0) {
                    unsigned target = 16u * (unsigned)t;
                    while (ld_acq(&g_gen8[w]) < target) { }
                }
                __syncwarp();
                const unsigned long long* hb = &g_ht2[(t - 1) & 1][32 * w][0];
                unsigned long long acc[16];
                #pragma unroll
                for (int r = 0; r < 16; r++) acc[r] = 0ull;
                #pragma unroll
                for (int half = 0; half < 2; half++) {
                    unsigned long long x[16];
                    #pragma unroll
                    for (int i = 0; i < 16; i++)
                        x[i] = __ldcg(&hb[(half * 16 + i) * BB + b]);
                    #pragma unroll
                    for (int i2 = 0; i2 < 8; i2++) {
                        unsigned long long xa = x[2 * i2], xb = x[2 * i2 + 1];
                        #pragma unroll
                        for (int r = 0; r < 16; r++) {
                            ulonglong2 wv = *(const ulonglong2*)
                                (w2_sh + r * 512 + 256 + 32 * w + 16 * half + 2 * i2);
                            acc[r] = ffma2u(xa, wv.x, ffma2u(xb, wv.y, acc[r]));
                        }
                    }
                }
                #pragma unroll
                for (int r = 0; r < 16; r++) {
                    F2U a; a.u = acc[r];
                    partf[r * 256 + w * 32 + b] = a.f.x + a.f.y;
                }
            } else {
                #pragma unroll
                for (int r = 0; r < 16; r++) partf[r * 256 + w * 32 + b] = 0.f;
            }
            bar_sync(1, 256);            // REC: partf visible

            if (tid < 128) {
                const int jj = tid >> 5;
                const int bb = tid & 31;
                float gs[4];
                #pragma unroll
                for (int g = 0; g < 4; g++) {
                    int r = g * 4 + jj;
                    float s = cns_sh[r * BB + bb] + ring[(t & 1) * 512 + r * 32 + bb];
                    #pragma unroll
                    for (int w2 = 0; w2 < 8; w2++) s += partf[r * 256 + w2 * 32 + bb];
                    gs[g] = s;
                }
                float ig = fast_sigmoid(gs[0]);
                float fg = fast_sigmoid(gs[1]);
                float gg = fast_tanh(gs[2]);
                float og = fast_sigmoid(gs[3]);
                float cc = fg * c0_sh[jj * BB + bb] + ig * gg;
                float hh = og * fast_tanh(cc);

                float* hp = (float*)&g_ht2[t & 1][2 * bid + (jj >> 1)][bb];
                hp[jj & 1] = hh;
                bar_sync(3, 128);        // reducers' h stores complete
                if (tid == 0) red_release_add(&g_gen8[bid >> 4], 1u);
                out[(size_t)bb * (SS * HH) + (size_t)t * HH + j0 + jj] = hh;
            }
        } else {
            // ================= EMB group: gates for t+1 =================
            if (t + 1 < SS) {
                const int et = tid - 256;     // 0..255
                const int we = et >> 5;       // 0..7
                unsigned long long acc[16];
                #pragma unroll
                for (int r = 0; r < 16; r++) acc[r] = 0ull;
                #pragma unroll
                for (int half = 0; half < 2; half++) {
                    unsigned long long x[16];
                    #pragma unroll
                    for (int ii = 0; ii < 16; ii++) {
                        int kp = 32 * we + 16 * half + ii;
                        x[ii] = x_sh[kp * 32 + (b ^ (kp & 31))];
                    }
                    #pragma unroll
                    for (int i2 = 0; i2 < 8; i2++) {
                        unsigned long long xa = x[2 * i2], xb = x[2 * i2 + 1];
                        #pragma unroll
                        for (int r = 0; r < 16; r++) {
                            ulonglong2 wv = *(const ulonglong2*)
                                (w2_sh + r * 512 + 32 * we + 16 * half + 2 * i2);
                            acc[r] = ffma2u(xa, wv.x, ffma2u(xb, wv.y, acc[r]));
                        }
                    }
                }
                #pragma unroll
                for (int r = 0; r < 16; r++) {
                    F2U a; a.u = acc[r];
                    epart[r * 256 + we * 32 + b] = a.f.x + a.f.y;
                }
                bar_sync(2, 256);        // EMB: epart visible, x reads done

                #pragma unroll
                for (int m = et; m < 512; m += 256) {
                    int row = m >> 5, bbe = m & 31;
                    float sum = 0.f;
                    #pragma unroll
                    for (int w2 = 0; w2 < 8; w2++)
                        sum += epart[row * 256 + w2 * 32 + bbe];
                    ring[((t + 1) & 1) * 512 + row * 32 + bbe] = sum;
                }

                // stage x <- tokens(t+2) (safe: all x reads done before bar 2)
                if (t + 2 < SS) {
                    #pragma unroll
                    for (int batch = 0; batch < 2; batch++) {
                        unsigned long long pr[16];
                        #pragma unroll
                        for (int q = 0; q < 16; q++) {
                            int r32 = batch * 16 + q;
                            int token = __ldg(&seq[r32 * SS + t + 2]);
                            pr[q] = __ldg((const unsigned long long*)
                                          (emb_table + (size_t)token * EE) + et);
                        }
                        #pragma unroll
                        for (int q = 0; q < 16; q++) {
                            int r32 = batch * 16 + q;
                            x_sh[et * 32 + (r32 ^ (et & 31))] = pr[q];
                        }
                    }
                }
            }
        }
        __syncthreads();   // end-of-step join: ring/x staging visible to all
    }
}

extern "C" void kernel_launch(void* const* d_in, const int* in_sizes, int n_in,
                              void* d_out, int out_size) {
    const int*   seq   = (const int*)d_in[0];
    // d_in[1] = enc_out : unused
    const float* enc_h = (const float*)d_in[2];
    const float* enc_c = (const float*)d_in[3];
    const float* emb   = (const float*)d_in[4];
    const float* W_ih  = (const float*)d_in[5];
    const float* W_hh  = (const float*)d_in[6];
    const float* b_ih  = (const float*)d_in[7];
    const float* b_hh  = (const float*)d_in[8];
    float* out = (float*)d_out;

    static bool attr_set = false;
    if (!attr_set) {
        cudaFuncSetAttribute(lstm_ws_kernel,
                             cudaFuncAttributeMaxDynamicSharedMemorySize, SMEM_TOT);
        attr_set = true;
    }

    reset_gen_kernel<<<1, 32>>>();
    lstm_ws_kernel<<<128, NTHR, SMEM_TOT>>>(seq, enc_h, enc_c, emb,
                                            W_ih, W_hh, b_ih, b_hh, out);
}